// round 1
// baseline (speedup 1.0000x reference)
#include <cuda_runtime.h>

#define BB 8
#define LL 1000000
#define KER 500
#define CC 8
#define OO 128
#define PTOT 16000
#define NP 10
#define NBLK (PTOT/NP)          /* 1600 */
#define SMEM_BYTES (NP*KER*CC*4) /* 160000 */

typedef unsigned long long ull;

// [conv][k][o][c] : 2*500*128*8 floats = 4 MB, L2-resident
__device__ float4 g_Wt4[2 * 500 * 128 * 2];
__device__ int   g_hmax[BB * OO];   // float bits, h >= 0 so int atomicMax is order-preserving
__device__ int   g_is64;

static __device__ __forceinline__ ull pk2(float x, float y) {
    ull r; asm("mov.b64 %0, {%1, %2};" : "=l"(r) : "f"(x), "f"(y)); return r;
}
static __device__ __forceinline__ void upk2(ull v, float &x, float &y) {
    asm("mov.b64 {%0, %1}, %2;" : "=f"(x), "=f"(y) : "l"(v));
}
static __device__ __forceinline__ void ffma2(ull &d, ull a, ull b) {
    asm("fma.rn.f32x2 %0, %1, %2, %0;" : "+l"(d) : "l"(a), "l"(b));
}

// ---------------------------------------------------------------------------
// Kernel 0: detect int64-vs-int32 delivery of x (jax x64 ambiguity) and zero
// the per-batch max accumulator. Deterministic: pure function of input bytes.
// If x is int64 (values 0..256), every odd 32-bit word is 0. If int32, the
// odd words are random tokens (P(all 2048 zero) ~ (1/257)^2048).
// ---------------------------------------------------------------------------
__global__ void k_detect_init(const int* __restrict__ x32) {
    __shared__ int s_nonzero;
    int t = threadIdx.x;
    if (t == 0) s_nonzero = 0;
    __syncthreads();
    int acc = 0;
    for (int i = t; i < 2048; i += 256) acc |= x32[2 * i + 1];
    if (acc) atomicOr(&s_nonzero, 1);
    for (int i = t; i < BB * OO; i += 256) g_hmax[i] = 0;
    __syncthreads();
    if (t == 0) g_is64 = (s_nonzero == 0) ? 1 : 0;
}

// ---------------------------------------------------------------------------
// Kernel 1: transpose W1,W2 [o][c][k] -> Wt [conv][k][o][c] so that lanes
// (consecutive o) issue coalesced LDG.128 in the main loop.
// ---------------------------------------------------------------------------
__global__ void k_prep(const float* __restrict__ W1, const float* __restrict__ W2) {
    float* Wt = (float*)g_Wt4;
    const int n = 2 * 500 * 128 * 8;
    for (int i = blockIdx.x * blockDim.x + threadIdx.x; i < n;
         i += gridDim.x * blockDim.x) {
        int c  = i & 7;
        int tt = i >> 3;
        int o  = tt & 127;
        tt >>= 7;
        int k    = tt % 500;
        int conv = tt / 500;
        const float* W = conv ? W2 : W1;
        Wt[i] = W[o * 4000 + c * 500 + k];
    }
}

// ---------------------------------------------------------------------------
// Kernel 2: main. One block = NP=10 patches x all 256 conv outputs.
// Thread t: o = t&127, k-half = t>>7 (k in [kh*250, kh*250+250)).
// Each thread computes BOTH convs for its o (E loaded once, 8 FFMA2 per
// patch per k). Embedded patches live in 160 KB smem (broadcast LDS.128).
// ---------------------------------------------------------------------------
extern __shared__ float s_mem[];

__global__ __launch_bounds__(256, 1)
void k_main(const void* __restrict__ xraw,
            const float* __restrict__ emb,
            const float* __restrict__ b1,
            const float* __restrict__ b2) {
    const int t   = threadIdx.x;
    const int o   = t & 127;
    const int kh  = t >> 7;
    const int pg0 = blockIdx.x * NP;
    const int is64 = g_is64;

    float* Es = s_mem;  // [NP][500][8]

    // ---- stage embedded patches into smem ----
    for (int idx = t; idx < NP * KER; idx += 256) {
        int p = idx / KER;
        int k = idx - p * KER;
        long long pos = (long long)(pg0 + p) * KER + k;
        int xi = is64 ? (int)((const long long*)xraw)[pos]
                      : ((const int*)xraw)[pos];
        xi = min(max(xi, 0), 256);  // emb[256] (pad) is the zero row
        const float4* er = (const float4*)(emb + (size_t)xi * 8);
        float4 ea = __ldg(er), eb = __ldg(er + 1);
        float4* dst = (float4*)(Es + (size_t)p * 4000 + k * 8);
        dst[0] = ea; dst[1] = eb;
    }
    __syncthreads();

    ull acc[2][NP][2];
#pragma unroll
    for (int cv = 0; cv < 2; ++cv)
#pragma unroll
        for (int p = 0; p < NP; ++p) { acc[cv][p][0] = 0ull; acc[cv][p][1] = 0ull; }

    const float4* Es4 = (const float4*)Es;
    const int k0 = kh * 250;

    for (int k = k0; k < k0 + 250; ++k) {
        const float4* w0 = g_Wt4 + ((size_t)k * 128 + o) * 2;       // conv 0
        float4 wa = __ldg(w0), wb = __ldg(w0 + 1);
        const float4* w1 = w0 + 500 * 128 * 2;                      // conv 1
        float4 va = __ldg(w1), vb = __ldg(w1 + 1);
        ull W00 = pk2(wa.x, wa.y), W01 = pk2(wa.z, wa.w);
        ull W02 = pk2(wb.x, wb.y), W03 = pk2(wb.z, wb.w);
        ull W10 = pk2(va.x, va.y), W11 = pk2(va.z, va.w);
        ull W12 = pk2(vb.x, vb.y), W13 = pk2(vb.z, vb.w);
#pragma unroll
        for (int p = 0; p < NP; ++p) {
            float4 ea = Es4[p * 1000 + 2 * k];
            float4 eb = Es4[p * 1000 + 2 * k + 1];
            ull E0 = pk2(ea.x, ea.y), E1 = pk2(ea.z, ea.w);
            ull E2 = pk2(eb.x, eb.y), E3 = pk2(eb.z, eb.w);
            ffma2(acc[0][p][0], E0, W00); ffma2(acc[0][p][1], E1, W01);
            ffma2(acc[0][p][0], E2, W02); ffma2(acc[0][p][1], E3, W03);
            ffma2(acc[1][p][0], E0, W10); ffma2(acc[1][p][1], E1, W11);
            ffma2(acc[1][p][0], E2, W12); ffma2(acc[1][p][1], E3, W13);
        }
    }

    __syncthreads();            // everyone done reading Es before overlay
    float* sPart = s_mem;       // [(kh*2+conv)][o][p] : 4*128*NP floats (20 KB)
#pragma unroll
    for (int cv = 0; cv < 2; ++cv)
#pragma unroll
        for (int p = 0; p < NP; ++p) {
            float x0, y0, x1, y1;
            upk2(acc[cv][p][0], x0, y0);
            upk2(acc[cv][p][1], x1, y1);
            sPart[((kh * 2 + cv) * 128 + o) * NP + p] = (x0 + y0) + (x1 + y1);
        }
    __syncthreads();

    if (t < 128) {
        float bb1 = b1[o], bb2 = b2[o];
        float hm = 0.f;
#pragma unroll
        for (int p = 0; p < NP; ++p) {
            float g1 = sPart[(0 * 128 + o) * NP + p] + sPart[(2 * 128 + o) * NP + p] + bb1;
            float g2 = sPart[(1 * 128 + o) * NP + p] + sPart[(3 * 128 + o) * NP + p] + bb2;
            float sg = 1.f / (1.f + __expf(-g2));
            float h  = fmaxf(g1, 0.f) * sg;   // relu(g1*sig) == max(g1,0)*sig, sig>0
            hm = fmaxf(hm, h);
        }
        int b = pg0 / (PTOT / BB);
        atomicMax(&g_hmax[b * OO + o], __float_as_int(hm));
    }
}

// ---------------------------------------------------------------------------
// Kernel 3: FC epilogue. 16 warps, one per (batch, class).
// ---------------------------------------------------------------------------
__global__ void k_fc(const float* __restrict__ fcW,
                     const float* __restrict__ fcb,
                     float* __restrict__ out) {
    int t = threadIdx.x, w = t >> 5, lane = t & 31;
    if (w < 16) {
        int b = w >> 1, cl = w & 1;
        float s = 0.f;
        for (int j = lane; j < OO; j += 32)
            s += fcW[cl * OO + j] * __int_as_float(g_hmax[b * OO + j]);
#pragma unroll
        for (int off = 16; off; off >>= 1)
            s += __shfl_down_sync(0xffffffffu, s, off);
        if (lane == 0) out[b * 2 + cl] = s + fcb[cl];
    }
}

// ---------------------------------------------------------------------------
extern "C" void kernel_launch(void* const* d_in, const int* in_sizes, int n_in,
                              void* d_out, int out_size) {
    const void*  x   = d_in[0];
    const float* emb = (const float*)d_in[1];
    const float* W1  = (const float*)d_in[2];
    const float* b1  = (const float*)d_in[3];
    const float* W2  = (const float*)d_in[4];
    const float* b2  = (const float*)d_in[5];
    const float* fcW = (const float*)d_in[6];
    const float* fcb = (const float*)d_in[7];
    float* out = (float*)d_out;

    cudaFuncSetAttribute(k_main, cudaFuncAttributeMaxDynamicSharedMemorySize,
                         SMEM_BYTES);

    k_detect_init<<<1, 256>>>((const int*)x);
    k_prep<<<512, 512>>>(W1, W2);
    k_main<<<NBLK, 256, SMEM_BYTES>>>(x, emb, b1, b2);
    k_fc<<<1, 512>>>(fcW, fcb, out);
}

// round 3
// speedup vs baseline: 2.6084x; 2.6084x over previous
#include <cuda_runtime.h>
#include <cuda_bf16.h>
#include <cstdint>

#define KER 500
#define OO 128
#define BB 8
#define PTOT 16000
#define MT 128              /* patches per CTA tile */
#define NBLK (PTOT/MT)      /* 125 */
#define NCH 64              /* K chunks of 64: K'=4096 */
#define STAGE_BYTES 98304   /* B hi 32K | B lo 32K | A hi 16K | A lo 16K */
#define DSMEM (2*STAGE_BYTES + 1024)

/* B pre-split & pre-swizzled: [chunk][half(hi/lo)][n=256][k=64] bf16 = 4 MB */
__device__ __nv_bfloat16 g_Bs[NCH * 2 * 256 * 64];
__device__ int g_hmax[BB * OO];
__device__ int g_is64;

/* ------------------------------------------------------------------ utils */
static __device__ __forceinline__ uint32_t s2u(const void* p) {
    uint32_t r;
    asm("{.reg .u64 t; cvta.to.shared.u64 t, %1; cvt.u32.u64 %0, t;}"
        : "=r"(r) : "l"(p));
    return r;
}
#define SWZ(b) ((b) ^ (((b) >> 3) & 0x70))

static __device__ __forceinline__ void ldsm4(uint32_t* r, uint32_t addr) {
    asm volatile("ldmatrix.sync.aligned.m8n8.x4.shared.b16 {%0,%1,%2,%3}, [%4];"
                 : "=r"(r[0]), "=r"(r[1]), "=r"(r[2]), "=r"(r[3]) : "r"(addr));
}
static __device__ __forceinline__ void mma_bf16(float* d, const uint32_t* a,
                                                uint32_t b0, uint32_t b1) {
    asm volatile(
        "mma.sync.aligned.m16n8k16.row.col.f32.bf16.bf16.f32 "
        "{%0,%1,%2,%3}, {%4,%5,%6,%7}, {%8,%9}, {%0,%1,%2,%3};"
        : "+f"(d[0]), "+f"(d[1]), "+f"(d[2]), "+f"(d[3])
        : "r"(a[0]), "r"(a[1]), "r"(a[2]), "r"(a[3]), "r"(b0), "r"(b1));
}
static __device__ __forceinline__ uint32_t pkbf(__nv_bfloat16 a, __nv_bfloat16 b) {
    return (uint32_t)__bfloat16_as_ushort(a) |
           ((uint32_t)__bfloat16_as_ushort(b) << 16);
}

/* --------------------------------------------------- kernel 0: detect+init */
__global__ void k_detect_init(const int* __restrict__ x32) {
    __shared__ int s_nonzero;
    int t = threadIdx.x;
    if (t == 0) s_nonzero = 0;
    __syncthreads();
    int acc = 0;
    for (int i = t; i < 2048; i += 256) acc |= x32[2 * i + 1];
    if (acc) atomicOr(&s_nonzero, 1);
    for (int i = t; i < BB * OO; i += 256) g_hmax[i] = 0;
    __syncthreads();
    if (t == 0) g_is64 = (s_nonzero == 0) ? 1 : 0;
}

/* ----------------------- kernel 1: split W1|W2 -> swizzled bf16 hi/lo in B */
__global__ void k_prep(const float* __restrict__ W1, const float* __restrict__ W2) {
    const int n = NCH * 2 * 256 * 64;
    for (int i = blockIdx.x * blockDim.x + threadIdx.x; i < n;
         i += gridDim.x * blockDim.x) {
        int k     = i & 63;
        int nr    = (i >> 6) & 255;
        int half  = (i >> 14) & 1;
        int chunk = i >> 15;
        int kc = chunk * 64 + k;
        float w = 0.f;
        if (kc < 4000) {
            int tok = kc >> 3, c = kc & 7;
            const float* W = (nr >= 128) ? W2 : W1;
            int o = nr & 127;
            w = W[o * 4000 + c * 500 + tok];
        }
        __nv_bfloat16 h = __float2bfloat16_rn(w);
        __nv_bfloat16 v = half ? __float2bfloat16_rn(w - __bfloat162float(h)) : h;
        uint32_t byte = (uint32_t)nr * 128 + (uint32_t)k * 2;
        uint32_t swz  = SWZ(byte);
        uint32_t base = ((uint32_t)chunk * 2 + half) * 32768;
        g_Bs[(base + swz) >> 1] = v;
    }
}

/* ---------------------------------------------- helpers for main pipeline */
static __device__ __forceinline__ void build_A(
    const void* xraw, const float* __restrict__ emb, int is64, int p0, int t,
    int chunk, uint32_t AhB, uint32_t AlB) {
    const int tok0 = chunk * 8;
#pragma unroll
    for (int it = 0; it < 2; ++it) {
        int idx = t + it * 512;
        int p = idx >> 3, j = idx & 7;
        int tok = tok0 + j;
        float4 ea = {0.f, 0.f, 0.f, 0.f}, eb = {0.f, 0.f, 0.f, 0.f};
        if (tok < KER) {
            size_t pos = (size_t)(p0 + p) * KER + tok;
            int xi = is64 ? (int)__ldg((const long long*)xraw + pos)
                          : __ldg((const int*)xraw + pos);
            xi = min(max(xi, 0), 256);
            const float4* er = (const float4*)(emb + (size_t)xi * 8);
            ea = __ldg(er); eb = __ldg(er + 1);
        }
        float v[8] = {ea.x, ea.y, ea.z, ea.w, eb.x, eb.y, eb.z, eb.w};
        uint32_t H[4], L[4];
#pragma unroll
        for (int c = 0; c < 4; c++) {
            __nv_bfloat16 h0 = __float2bfloat16_rn(v[2 * c]);
            __nv_bfloat16 h1 = __float2bfloat16_rn(v[2 * c + 1]);
            __nv_bfloat16 l0 = __float2bfloat16_rn(v[2 * c] - __bfloat162float(h0));
            __nv_bfloat16 l1 = __float2bfloat16_rn(v[2 * c + 1] - __bfloat162float(h1));
            H[c] = pkbf(h0, h1); L[c] = pkbf(l0, l1);
        }
        uint32_t byte = (uint32_t)p * 128 + (uint32_t)j * 16;
        uint32_t sw = SWZ(byte);
        asm volatile("st.shared.v4.b32 [%0], {%1,%2,%3,%4};"
                     :: "r"(AhB + sw), "r"(H[0]), "r"(H[1]), "r"(H[2]), "r"(H[3])
                     : "memory");
        asm volatile("st.shared.v4.b32 [%0], {%1,%2,%3,%4};"
                     :: "r"(AlB + sw), "r"(L[0]), "r"(L[1]), "r"(L[2]), "r"(L[3])
                     : "memory");
    }
}

static __device__ __forceinline__ void load_B(int chunk, int t, uint32_t Bst) {
    const char* src = (const char*)g_Bs + (size_t)chunk * 65536 + (size_t)t * 16;
    uint32_t dst = Bst + (uint32_t)t * 16;
#pragma unroll
    for (int it = 0; it < 8; ++it)
        asm volatile("cp.async.cg.shared.global [%0], [%1], 16;"
                     :: "r"(dst + it * 8192), "l"(src + (size_t)it * 8192)
                     : "memory");
    asm volatile("cp.async.commit_group;" ::: "memory");
}

/* ------------------------------------------------------ kernel 2: the GEMM */
extern __shared__ char dsm_raw[];

__global__ __launch_bounds__(512, 1)
void k_main(const void* __restrict__ xraw, const float* __restrict__ emb,
            const float* __restrict__ b1, const float* __restrict__ b2) {
    __shared__ int s_hmax[BB][OO];

    const int t = threadIdx.x;
    const int lane = t & 31, wid = t >> 5;
    const int wm = wid & 3, wn = wid >> 2;     /* 4 x 4 warp grid */
    const int p0 = blockIdx.x * MT;
    const int is64 = g_is64;

    char* dptr = (char*)((((uintptr_t)dsm_raw) + 1023) & ~(uintptr_t)1023);
    const uint32_t dbase = s2u(dptr);

    for (int i = t; i < BB * OO; i += 512) ((int*)s_hmax)[i] = 0;

    /* per-thread ldmatrix row-base byte offsets (within hi/lo blocks) */
    const int lr = lane & 15, seg = lane >> 4;
    uint32_t aRow[2], bRow[2][2];
#pragma unroll
    for (int mt = 0; mt < 2; ++mt)
        aRow[mt] = (uint32_t)(wm * 32 + mt * 16 + lr) * 128 + seg * 16;
#pragma unroll
    for (int h = 0; h < 2; ++h)
#pragma unroll
        for (int pr = 0; pr < 2; ++pr)
            bRow[h][pr] = (uint32_t)(wn * 64 + h * 32 + pr * 16 + lr) * 128 + seg * 16;

    float acc[2][8][4];
#pragma unroll
    for (int a = 0; a < 2; ++a)
#pragma unroll
        for (int b = 0; b < 8; ++b)
#pragma unroll
            for (int c = 0; c < 4; ++c) acc[a][b][c] = 0.f;

    /* preamble: stage 0 */
    {
        uint32_t sb = dbase;
        load_B(0, t, sb);
        build_A(xraw, emb, is64, p0, t, 0, sb + 65536, sb + 81920);
    }

    int s = 0;
    for (int i = 0; i < NCH; ++i) {
        asm volatile("cp.async.wait_group 0;" ::: "memory");
        __syncthreads();
        const uint32_t sb = dbase + (uint32_t)s * STAGE_BYTES;
        if (i + 1 < NCH) {
            const uint32_t nb = dbase + (uint32_t)(s ^ 1) * STAGE_BYTES;
            load_B(i + 1, t, nb);
            build_A(xraw, emb, is64, p0, t, i + 1, nb + 65536, nb + 81920);
        }
        const uint32_t Bh = sb, Bl = sb + 32768;
        const uint32_t Ah = sb + 65536, Al = sb + 81920;
#pragma unroll
        for (int ks = 0; ks < 4; ++ks) {
            const uint32_t kb = (uint32_t)ks * 32;
            uint32_t fAh[2][4], fAl[2][4];
#pragma unroll
            for (int mt = 0; mt < 2; ++mt) {
                ldsm4(fAh[mt], Ah + SWZ(aRow[mt] + kb));
                ldsm4(fAl[mt], Al + SWZ(aRow[mt] + kb));
            }
#pragma unroll
            for (int h = 0; h < 2; ++h) {
                uint32_t fBh[2][4], fBl[2][4];
#pragma unroll
                for (int pr = 0; pr < 2; ++pr) {
                    ldsm4(fBh[pr], Bh + SWZ(bRow[h][pr] + kb));
                    ldsm4(fBl[pr], Bl + SWZ(bRow[h][pr] + kb));
                }
#pragma unroll
                for (int mt = 0; mt < 2; ++mt)
#pragma unroll
                    for (int pr = 0; pr < 2; ++pr) {
                        const int nt0 = h * 4 + pr * 2;
                        /* tile q=0: rows n0-7 -> regs {0,2}; q=1: {1,3} */
                        mma_bf16(acc[mt][nt0], fAh[mt], fBh[pr][0], fBh[pr][2]);
                        mma_bf16(acc[mt][nt0], fAh[mt], fBl[pr][0], fBl[pr][2]);
                        mma_bf16(acc[mt][nt0], fAl[mt], fBh[pr][0], fBh[pr][2]);
                        mma_bf16(acc[mt][nt0 + 1], fAh[mt], fBh[pr][1], fBh[pr][3]);
                        mma_bf16(acc[mt][nt0 + 1], fAh[mt], fBl[pr][1], fBl[pr][3]);
                        mma_bf16(acc[mt][nt0 + 1], fAl[mt], fBh[pr][1], fBh[pr][3]);
                    }
            }
        }
        s ^= 1;
    }

    /* --------------------------- epilogue: accums -> smem gbuf[128][256] */
    __syncthreads();
    float* gbuf = (float*)dptr;
    {
        const int r0 = lane >> 2, c0 = (lane & 3) * 2;
#pragma unroll
        for (int mt = 0; mt < 2; ++mt) {
            const int m = wm * 32 + mt * 16;
#pragma unroll
            for (int j = 0; j < 8; ++j) {
                const int n = wn * 64 + (j >> 2) * 32 + (j & 3) * 8 + c0;
                gbuf[(m + r0) * 256 + n]     = acc[mt][j][0];
                gbuf[(m + r0) * 256 + n + 1] = acc[mt][j][1];
                gbuf[(m + r0 + 8) * 256 + n]     = acc[mt][j][2];
                gbuf[(m + r0 + 8) * 256 + n + 1] = acc[mt][j][3];
            }
        }
    }
    __syncthreads();

    /* GLU + per-CTA max */
    {
        const int o = t & 127, pg = t >> 7;
#pragma unroll 8
        for (int j = 0; j < 32; ++j) {
            const int p = pg * 32 + j;
            float g1 = gbuf[p * 256 + o] + __ldg(b1 + o);
            float g2 = gbuf[p * 256 + o + 128] + __ldg(b2 + o);
            float h = fmaxf(g1, 0.f) * (1.f / (1.f + __expf(-g2)));
            const int b = (p0 + p) / 2000;
            atomicMax(&s_hmax[b][o], __float_as_int(h));
        }
    }
    __syncthreads();

    /* flush to global */
    {
        const int blo = p0 / 2000, bhi = (p0 + MT - 1) / 2000;
        if (t < 256) {
            const int o = t & 127, which = t >> 7;
            const int b = which ? bhi : blo;
            if (which == 0 || bhi != blo)
                atomicMax(&g_hmax[b * OO + o], s_hmax[b][o]);
        }
    }
}

/* ---------------------------------------------------- kernel 3: FC epilog */
__global__ void k_fc(const float* __restrict__ fcW,
                     const float* __restrict__ fcb, float* __restrict__ out) {
    int t = threadIdx.x, w = t >> 5, lane = t & 31;
    if (w < 16) {
        int b = w >> 1, cl = w & 1;
        float s = 0.f;
        for (int j = lane; j < OO; j += 32)
            s += fcW[cl * OO + j] * __int_as_float(g_hmax[b * OO + j]);
#pragma unroll
        for (int off = 16; off; off >>= 1)
            s += __shfl_down_sync(0xffffffffu, s, off);
        if (lane == 0) out[b * 2 + cl] = s + fcb[cl];
    }
}

/* ------------------------------------------------------------------------ */
extern "C" void kernel_launch(void* const* d_in, const int* in_sizes, int n_in,
                              void* d_out, int out_size) {
    const void*  x   = d_in[0];
    const float* emb = (const float*)d_in[1];
    const float* W1  = (const float*)d_in[2];
    const float* b1  = (const float*)d_in[3];
    const float* W2  = (const float*)d_in[4];
    const float* b2  = (const float*)d_in[5];
    const float* fcW = (const float*)d_in[6];
    const float* fcb = (const float*)d_in[7];
    float* out = (float*)d_out;

    cudaFuncSetAttribute(k_main, cudaFuncAttributeMaxDynamicSharedMemorySize,
                         DSMEM);

    k_detect_init<<<1, 256>>>((const int*)x);
    k_prep<<<256, 256>>>(W1, W2);
    k_main<<<NBLK, 512, DSMEM>>>(x, emb, b1, b2);
    k_fc<<<1, 512>>>(fcW, fcb, out);
}

// round 5
// speedup vs baseline: 2.8798x; 1.1041x over previous
#include <cuda_runtime.h>
#include <cuda_bf16.h>
#include <cstdint>

#define KER 500
#define OO 128
#define BB 8
#define PTOT 16000
#define MT 128              /* patches per CTA tile */
#define NBLK (PTOT/MT)      /* 125 */
#define NCH 64              /* K chunks of 64: K'=4096 */
#define STAGE_BYTES 98304   /* B hi 32K | B lo 32K | A hi 16K | A lo 16K */
#define DSMEM (2*STAGE_BYTES + 1024)

/* B pre-split & pre-swizzled: [chunk][half(hi/lo)][n=256][k=64] bf16 = 4 MB */
__device__ __nv_bfloat16 g_Bs[NCH * 2 * 256 * 64];
__device__ int g_hmax[BB * OO];

/* ------------------------------------------------------------------ utils */
static __device__ __forceinline__ uint32_t s2u(const void* p) {
    uint32_t r;
    asm("{.reg .u64 t; cvta.to.shared.u64 t, %1; cvt.u32.u64 %0, t;}"
        : "=r"(r) : "l"(p));
    return r;
}
#define SWZ(b) ((b) ^ (((b) >> 3) & 0x70))

static __device__ __forceinline__ void ldsm4(uint32_t* r, uint32_t addr) {
    asm volatile("ldmatrix.sync.aligned.m8n8.x4.shared.b16 {%0,%1,%2,%3}, [%4];"
                 : "=r"(r[0]), "=r"(r[1]), "=r"(r[2]), "=r"(r[3]) : "r"(addr));
}
static __device__ __forceinline__ void mma_bf16(float* d, const uint32_t* a,
                                                uint32_t b0, uint32_t b1) {
    asm volatile(
        "mma.sync.aligned.m16n8k16.row.col.f32.bf16.bf16.f32 "
        "{%0,%1,%2,%3}, {%4,%5,%6,%7}, {%8,%9}, {%0,%1,%2,%3};"
        : "+f"(d[0]), "+f"(d[1]), "+f"(d[2]), "+f"(d[3])
        : "r"(a[0]), "r"(a[1]), "r"(a[2]), "r"(a[3]), "r"(b0), "r"(b1));
}
static __device__ __forceinline__ uint32_t pkbf(__nv_bfloat16 a, __nv_bfloat16 b) {
    return (uint32_t)__bfloat16_as_ushort(a) |
           ((uint32_t)__bfloat16_as_ushort(b) << 16);
}

/* ----------------------- kernel 1: split W1|W2 -> swizzled bf16 hi/lo in B */
__global__ void k_prep(const float* __restrict__ W1, const float* __restrict__ W2) {
    if (blockIdx.x == 0)
        for (int i = threadIdx.x; i < BB * OO; i += blockDim.x) g_hmax[i] = 0;
    const int n = NCH * 2 * 256 * 64;
    for (int i = blockIdx.x * blockDim.x + threadIdx.x; i < n;
         i += gridDim.x * blockDim.x) {
        int k     = i & 63;
        int nr    = (i >> 6) & 255;
        int half  = (i >> 14) & 1;
        int chunk = i >> 15;
        int kc = chunk * 64 + k;
        float w = 0.f;
        if (kc < 4000) {
            int tok = kc >> 3, c = kc & 7;
            const float* W = (nr >= 128) ? W2 : W1;
            int o = nr & 127;
            w = W[o * 4000 + c * 500 + tok];
        }
        __nv_bfloat16 h = __float2bfloat16_rn(w);
        __nv_bfloat16 v = half ? __float2bfloat16_rn(w - __bfloat162float(h)) : h;
        uint32_t byte = (uint32_t)nr * 128 + (uint32_t)k * 2;
        uint32_t base = ((uint32_t)chunk * 2 + half) * 32768;
        g_Bs[(base + SWZ(byte)) >> 1] = v;
    }
}

/* ---------------------------------------------- helpers for main pipeline */
static __device__ __forceinline__ void prefetch_x(const void* xraw, int is64,
                                                  int p0, int t, int chunk,
                                                  int* xi) {
#pragma unroll
    for (int it = 0; it < 2; ++it) {
        const int idx = t + it * 512;
        const int p = idx >> 3, j = idx & 7;
        const int tok = chunk * 8 + j;
        int v = 256;               /* emb[256] is the all-zero pad row */
        if (tok < KER) {
            size_t pos = (size_t)(p0 + p) * KER + tok;
            v = is64 ? (int)__ldg((const long long*)xraw + pos)
                     : __ldg((const int*)xraw + pos);
            v = min(max(v, 0), 256);
        }
        xi[it] = v;
    }
}

static __device__ __forceinline__ void build_A(const float* __restrict__ emb,
                                               const int* xi, int t,
                                               uint32_t AhB, uint32_t AlB) {
#pragma unroll
    for (int it = 0; it < 2; ++it) {
        const int idx = t + it * 512;
        const int p = idx >> 3, j = idx & 7;
        const float4* er = (const float4*)(emb + (size_t)xi[it] * 8);
        float4 ea = __ldg(er), eb = __ldg(er + 1);
        float v[8] = {ea.x, ea.y, ea.z, ea.w, eb.x, eb.y, eb.z, eb.w};
        uint32_t H[4], L[4];
#pragma unroll
        for (int c = 0; c < 4; c++) {
            __nv_bfloat16 h0 = __float2bfloat16_rn(v[2 * c]);
            __nv_bfloat16 h1 = __float2bfloat16_rn(v[2 * c + 1]);
            __nv_bfloat16 l0 = __float2bfloat16_rn(v[2 * c] - __bfloat162float(h0));
            __nv_bfloat16 l1 = __float2bfloat16_rn(v[2 * c + 1] - __bfloat162float(h1));
            H[c] = pkbf(h0, h1); L[c] = pkbf(l0, l1);
        }
        const uint32_t sw = SWZ((uint32_t)p * 128 + (uint32_t)j * 16);
        asm volatile("st.shared.v4.b32 [%0], {%1,%2,%3,%4};"
                     :: "r"(AhB + sw), "r"(H[0]), "r"(H[1]), "r"(H[2]), "r"(H[3])
                     : "memory");
        asm volatile("st.shared.v4.b32 [%0], {%1,%2,%3,%4};"
                     :: "r"(AlB + sw), "r"(L[0]), "r"(L[1]), "r"(L[2]), "r"(L[3])
                     : "memory");
    }
}

static __device__ __forceinline__ void load_B(int chunk, int t, uint32_t Bst) {
    const char* src = (const char*)g_Bs + (size_t)chunk * 65536 + (size_t)t * 16;
    uint32_t dst = Bst + (uint32_t)t * 16;
#pragma unroll
    for (int it = 0; it < 8; ++it)
        asm volatile("cp.async.cg.shared.global [%0], [%1], 16;"
                     :: "r"(dst + it * 8192), "l"(src + (size_t)it * 8192)
                     : "memory");
    asm volatile("cp.async.commit_group;" ::: "memory");
}

/* ------------------------------------------------------ kernel 2: the GEMM */
extern __shared__ char dsm_raw[];

__global__ __launch_bounds__(512, 1)
void k_main(const void* __restrict__ xraw, const float* __restrict__ emb,
            const float* __restrict__ b1, const float* __restrict__ b2) {
    __shared__ int s_hmax[BB][OO];
    __shared__ int s_flag;

    const int t = threadIdx.x;
    const int lane = t & 31, wid = t >> 5;
    const int wm = wid & 3, wn = wid >> 2;     /* 4 x 4 warp grid */
    const int p0 = blockIdx.x * MT;

    char* dptr = (char*)((((uintptr_t)dsm_raw) + 1023) & ~(uintptr_t)1023);
    const uint32_t dbase = s2u(dptr);

    /* is64 detect (first 512 odd 32-bit words; all-zero iff int64) + init */
    if (t == 0) s_flag = 0;
    for (int i = t; i < BB * OO; i += 512) ((int*)s_hmax)[i] = 0;
    __syncthreads();
    if (((const int*)xraw)[2 * t + 1] != 0) s_flag = 1;
    __syncthreads();
    const int is64 = (s_flag == 0);

    /* per-thread ldmatrix row-base byte offsets (within hi/lo blocks) */
    const int lr = lane & 15, seg = lane >> 4;
    const uint32_t aRow0 = (uint32_t)(wm * 32 + lr) * 128 + seg * 16;
    const uint32_t aRow1 = aRow0 + 16 * 128;
    uint32_t bRow[4];   /* [h*2+pr] */
#pragma unroll
    for (int q = 0; q < 4; ++q)
        bRow[q] = (uint32_t)(wn * 64 + (q >> 1) * 32 + (q & 1) * 16 + lr) * 128 +
                  seg * 16;

    float acc[2][8][4];
#pragma unroll
    for (int a = 0; a < 2; ++a)
#pragma unroll
        for (int b = 0; b < 8; ++b)
#pragma unroll
            for (int c = 0; c < 4; ++c) acc[a][b][c] = 0.f;

    /* preamble: stage 0 */
    int xi[2];
    load_B(0, t, dbase);
    prefetch_x(xraw, is64, p0, t, 0, xi);
    build_A(emb, xi, t, dbase + 65536, dbase + 81920);
    prefetch_x(xraw, is64, p0, t, 1, xi);

    int s = 0;
    for (int i = 0; i < NCH; ++i) {
        asm volatile("cp.async.wait_group 0;" ::: "memory");
        __syncthreads();
        const uint32_t sb = dbase + (uint32_t)s * STAGE_BYTES;
        const uint32_t nb = dbase + (uint32_t)(s ^ 1) * STAGE_BYTES;
        if (i + 1 < NCH) load_B(i + 1, t, nb);

        const uint32_t Bh = sb, Bl = sb + 32768;
        const uint32_t Ah = sb + 65536, Al = sb + 81920;
#pragma unroll
        for (int ks = 0; ks < 4; ++ks) {
            const uint32_t kb = (uint32_t)ks * 32;
            uint32_t fAh0[4], fAh1[4], fAl0[4], fAl1[4];
            ldsm4(fAh0, Ah + SWZ(aRow0 + kb));
            ldsm4(fAh1, Ah + SWZ(aRow1 + kb));
            ldsm4(fAl0, Al + SWZ(aRow0 + kb));
            ldsm4(fAl1, Al + SWZ(aRow1 + kb));
#pragma unroll
            for (int q = 0; q < 4; ++q) {
                uint32_t bh[4], bl[4];
                ldsm4(bh, Bh + SWZ(bRow[q] + kb));
                ldsm4(bl, Bl + SWZ(bRow[q] + kb));
                const int nt0 = (q >> 1) * 4 + (q & 1) * 2;
                mma_bf16(acc[0][nt0], fAh0, bh[0], bh[2]);
                mma_bf16(acc[0][nt0], fAh0, bl[0], bl[2]);
                mma_bf16(acc[0][nt0], fAl0, bh[0], bh[2]);
                mma_bf16(acc[0][nt0 + 1], fAh0, bh[1], bh[3]);
                mma_bf16(acc[0][nt0 + 1], fAh0, bl[1], bl[3]);
                mma_bf16(acc[0][nt0 + 1], fAl0, bh[1], bh[3]);
                mma_bf16(acc[1][nt0], fAh1, bh[0], bh[2]);
                mma_bf16(acc[1][nt0], fAh1, bl[0], bl[2]);
                mma_bf16(acc[1][nt0], fAl1, bh[0], bh[2]);
                mma_bf16(acc[1][nt0 + 1], fAh1, bh[1], bh[3]);
                mma_bf16(acc[1][nt0 + 1], fAh1, bl[1], bl[3]);
                mma_bf16(acc[1][nt0 + 1], fAl1, bh[1], bh[3]);
            }
        }
        if (i + 1 < NCH) {
            build_A(emb, xi, t, nb + 65536, nb + 81920);
            if (i + 2 < NCH) prefetch_x(xraw, is64, p0, t, i + 2, xi);
        }
        s ^= 1;
    }

    /* --------------------------- epilogue: accums -> smem gbuf[128][256] */
    __syncthreads();
    float* gbuf = (float*)dptr;
    {
        const int r0 = lane >> 2, c0 = (lane & 3) * 2;
#pragma unroll
        for (int mt = 0; mt < 2; ++mt) {
            const int m = wm * 32 + mt * 16;
#pragma unroll
            for (int j = 0; j < 8; ++j) {
                const int n = wn * 64 + (j >> 2) * 32 + (j & 3) * 8 + c0;
                gbuf[(m + r0) * 256 + n]     = acc[mt][j][0];
                gbuf[(m + r0) * 256 + n + 1] = acc[mt][j][1];
                gbuf[(m + r0 + 8) * 256 + n]     = acc[mt][j][2];
                gbuf[(m + r0 + 8) * 256 + n + 1] = acc[mt][j][3];
            }
        }
    }
    __syncthreads();

    /* GLU + per-CTA max */
    {
        const int o = t & 127, pg = t >> 7;
#pragma unroll 8
        for (int j = 0; j < 32; ++j) {
            const int p = pg * 32 + j;
            float g1 = gbuf[p * 256 + o] + __ldg(b1 + o);
            float g2 = gbuf[p * 256 + o + 128] + __ldg(b2 + o);
            float h = fmaxf(g1, 0.f) * (1.f / (1.f + __expf(-g2)));
            const int b = (p0 + p) / 2000;
            atomicMax(&s_hmax[b][o], __float_as_int(h));
        }
    }
    __syncthreads();

    /* flush to global */
    {
        const int blo = p0 / 2000, bhi = (p0 + MT - 1) / 2000;
        if (t < 256) {
            const int o = t & 127, which = t >> 7;
            const int b = which ? bhi : blo;
            if (which == 0 || bhi != blo)
                atomicMax(&g_hmax[b * OO + o], s_hmax[b][o]);
        }
    }
}

/* ---------------------------------------------------- kernel 3: FC epilog */
__global__ void k_fc(const float* __restrict__ fcW,
                     const float* __restrict__ fcb, float* __restrict__ out) {
    int t = threadIdx.x, w = t >> 5, lane = t & 31;
    if (w < 16) {
        int b = w >> 1, cl = w & 1;
        float s = 0.f;
        for (int j = lane; j < OO; j += 32)
            s += fcW[cl * OO + j] * __int_as_float(g_hmax[b * OO + j]);
#pragma unroll
        for (int off = 16; off; off >>= 1)
            s += __shfl_down_sync(0xffffffffu, s, off);
        if (lane == 0) out[b * 2 + cl] = s + fcb[cl];
    }
}

/* ------------------------------------------------------------------------ */
extern "C" void kernel_launch(void* const* d_in, const int* in_sizes, int n_in,
                              void* d_out, int out_size) {
    const void*  x   = d_in[0];
    const float* emb = (const float*)d_in[1];
    const float* W1  = (const float*)d_in[2];
    const float* b1  = (const float*)d_in[3];
    const float* W2  = (const float*)d_in[4];
    const float* b2  = (const float*)d_in[5];
    const float* fcW = (const float*)d_in[6];
    const float* fcb = (const float*)d_in[7];
    float* out = (float*)d_out;

    cudaFuncSetAttribute(k_main, cudaFuncAttributeMaxDynamicSharedMemorySize,
                         DSMEM);

    k_prep<<<256, 256>>>(W1, W2);
    k_main<<<NBLK, 512, DSMEM>>>(x, emb, b1, b2);
    k_fc<<<1, 512>>>(fcW, fcb, out);
}